// round 5
// baseline (speedup 1.0000x reference)
#include <cuda_runtime.h>
#include <math.h>

#define D 8192
#define M_TIME 16
#define RMS_EPS 1e-6f
#define DEN_EPS 1e-9f
#define KTOP 1024  // D/8

// Scratch (no allocations allowed)
__device__ __align__(16) float g_x[D];
__device__ __align__(16) float g_r[D];
__device__ __align__(16) float g_k[D];
__device__ __align__(16) float g_v[D];
__device__ __align__(16) float g_y[D];
__device__ __align__(16) float g_h[D];
__device__ unsigned g_cnt1 = 0;   // mv3 completion counter
__device__ unsigned g_cnt2 = 0;   // mv_o completion counter

__device__ __forceinline__ float warp_sum(float v) {
    #pragma unroll
    for (int o = 16; o > 0; o >>= 1) v += __shfl_down_sync(0xffffffffu, v, o);
    return v;
}

// ---------------------------------------------------------------------------
// K1: x = rmsnorm(x_in + pred) * norm_w      (1 block, 1024 threads)
// ---------------------------------------------------------------------------
__global__ void k_rms(const float* __restrict__ x_in,
                      const float* __restrict__ pred,
                      const float* __restrict__ norm_w) {
    __shared__ float sh[32];
    __shared__ float s_inv;
    const int t = threadIdx.x;  // 1024
    float vals[8];
    float acc = 0.f;
    #pragma unroll
    for (int j = 0; j < 8; j++) {
        int i = t + j * 1024;
        float a = x_in[i] + pred[i];
        vals[j] = a;
        acc = fmaf(a, a, acc);
    }
    acc = warp_sum(acc);
    const int lane = t & 31, wid = t >> 5;
    if (lane == 0) sh[wid] = acc;
    __syncthreads();
    if (wid == 0) {
        float v = sh[lane];
        v = warp_sum(v);
        if (lane == 0) s_inv = rsqrtf(v * (1.0f / D) + RMS_EPS);
    }
    __syncthreads();
    const float inv = s_inv;
    #pragma unroll
    for (int j = 0; j < 8; j++) {
        int i = t + j * 1024;
        g_x[i] = vals[j] * inv * norm_w[i];
    }
}

// ---------------------------------------------------------------------------
// K2: r = sigmoid(Wr@x), k = Wk@x, v = Wv@x   (3*8192 blocks, 256 threads)
//     Last finishing block also runs the decay/RoPE/gating -> y.
// ---------------------------------------------------------------------------
__global__ void __launch_bounds__(256, 8) k_mv3(const float* __restrict__ Wr,
                                                const float* __restrict__ Wk,
                                                const float* __restrict__ Wv,
                                                const float* __restrict__ state_num,
                                                const float* __restrict__ state_den,
                                                const float* __restrict__ decay_param,
                                                const float* __restrict__ W_time,
                                                const float* __restrict__ step_pos,
                                                const int*   __restrict__ dt) {
    const int bid = blockIdx.x;
    const int mat = bid >> 13;           // 0..2
    const int row = bid & (D - 1);
    const float* W = (mat == 0 ? Wr : (mat == 1 ? Wk : Wv)) + (size_t)row * D;
    const float4* __restrict__ W4 = (const float4*)W;
    const float4* __restrict__ X4 = (const float4*)g_x;

    const int t = threadIdx.x;
    float acc = 0.f;
    #pragma unroll
    for (int j = 0; j < D / 4 / 256; j++) {  // 8 iterations
        int idx = t + j * 256;
        float4 w = W4[idx];
        float4 x = X4[idx];
        acc = fmaf(w.x, x.x, acc);
        acc = fmaf(w.y, x.y, acc);
        acc = fmaf(w.z, x.z, acc);
        acc = fmaf(w.w, x.w, acc);
    }
    __shared__ float sh[8];
    acc = warp_sum(acc);
    const int lane = t & 31, wid = t >> 5;
    if (lane == 0) sh[wid] = acc;
    __syncthreads();
    if (t == 0) {
        float s = sh[0];
        #pragma unroll
        for (int i = 1; i < 8; i++) s += sh[i];
        if (mat == 0)      g_r[row] = 1.0f / (1.0f + __expf(-s));
        else if (mat == 1) g_k[row] = s;
        else               g_v[row] = s;
    }

    // ---- last-block gate fusion (threadFenceReduction pattern) ----
    __shared__ unsigned s_rank;
    __threadfence();
    if (t == 0) s_rank = atomicAdd(&g_cnt1, 1u);
    __syncthreads();
    if (s_rank == gridDim.x - 1) {
        if (t == 0) g_cnt1 = 0;         // reset for next graph replay
        __threadfence();
        const int n = dt[0];
        const float sp = step_pos[0];
        #pragma unroll
        for (int j = 0; j < D / 256; j++) {       // 32 elems/thread
            int i = t + j * 256;
            float sg = 1.0f / (1.0f + expf(-decay_param[i]));
            float lam = sg * sg;
            float mul = 1.0f;
            for (int q = 0; q < n; q++) mul *= lam;

            float v = g_v[i];
            if (i < 2 * M_TIME) {
                int p = i >> 1;
                float th = sp * W_time[p];
                float c, sn_;
                sincosf(th, &sn_, &c);
                float v0 = g_v[2 * p];
                float v1 = g_v[2 * p + 1];
                v = (i & 1) ? (v0 * sn_ + v1 * c) : (v0 * c - v1 * sn_);
            }
            float w = expf(g_k[i]);
            float num = state_num[i] * mul * lam + w * v;
            float den = state_den[i] * mul * lam + w;
            g_y[i] = g_r[i] * (num / (den + DEN_EPS));
        }
    }
}

// ---------------------------------------------------------------------------
// K3: h = x + Wo@y  (8192 blocks, 256 threads)
//     Last finishing block also runs kWTA (radix select + threshold write).
// ---------------------------------------------------------------------------
__global__ void __launch_bounds__(256, 8) k_mv_o(const float* __restrict__ Wo,
                                                 float* __restrict__ out) {
    const int row = blockIdx.x;
    const float4* __restrict__ W4 = (const float4*)(Wo + (size_t)row * D);
    const float4* __restrict__ Y4 = (const float4*)g_y;

    const int t = threadIdx.x;
    float acc = 0.f;
    #pragma unroll
    for (int j = 0; j < D / 4 / 256; j++) {
        int idx = t + j * 256;
        float4 w = W4[idx];
        float4 y = Y4[idx];
        acc = fmaf(w.x, y.x, acc);
        acc = fmaf(w.y, y.y, acc);
        acc = fmaf(w.z, y.z, acc);
        acc = fmaf(w.w, y.w, acc);
    }
    __shared__ float shr[8];
    acc = warp_sum(acc);
    const int lane = t & 31, wid = t >> 5;
    if (lane == 0) shr[wid] = acc;
    __syncthreads();
    if (t == 0) {
        float s = shr[0];
        #pragma unroll
        for (int i = 1; i < 8; i++) s += shr[i];
        g_h[row] = g_x[row] + s;
    }

    // ---- last-block kWTA fusion ----
    __shared__ unsigned s_rank;
    __threadfence();
    if (t == 0) s_rank = atomicAdd(&g_cnt2, 1u);
    __syncthreads();
    if (s_rank != gridDim.x - 1) return;
    if (t == 0) g_cnt2 = 0;             // reset for next graph replay
    __threadfence();

    __shared__ unsigned hist[256];
    __shared__ unsigned wsum[8];
    __shared__ unsigned s_prefix, s_k;

    unsigned prefix = 0;
    unsigned kk = KTOP;
    #pragma unroll 1
    for (int shift = 24; shift >= 0; shift -= 8) {
        hist[t] = 0;
        __syncthreads();
        unsigned mask = (shift == 24) ? 0u : (~0u << (shift + 8));
        #pragma unroll
        for (int j = 0; j < D / 256; j++) {       // 32 elems/thread, re-read (cached)
            unsigned b = __float_as_uint(fabsf(g_h[t + j * 256]));
            if ((b & mask) == prefix)
                atomicAdd(&hist[(b >> shift) & 255u], 1u);
        }
        __syncthreads();
        {
            // Inclusive suffix sum S[t] = sum_{i>=t} hist[i] over 256 buckets.
            unsigned h = hist[t];
            unsigned v = h;
            #pragma unroll
            for (int o = 1; o < 32; o <<= 1) {
                unsigned u = __shfl_down_sync(0xffffffffu, v, o);
                if (lane + o < 32) v += u;
            }
            if (lane == 0) wsum[wid] = v;
            __syncthreads();
            unsigned hi = 0;
            #pragma unroll
            for (int w = 0; w < 8; w++)
                if (w > wid) hi += wsum[w];
            unsigned S = v + hi;          // inclusive suffix sum at t
            if (S >= kk && (S - h) < kk) {
                s_prefix = prefix | ((unsigned)t << shift);
                s_k = kk - (S - h);
            }
        }
        __syncthreads();
        prefix = s_prefix;
        kk = s_k;
        __syncthreads();
    }

    const float thr = __uint_as_float(prefix);
    #pragma unroll
    for (int j = 0; j < D / 256; j++) {
        int i = t + j * 256;
        float h = g_h[i];
        out[i] = (fabsf(h) >= thr) ? h : 0.0f;
    }
}

// ---------------------------------------------------------------------------
extern "C" void kernel_launch(void* const* d_in, const int* in_sizes, int n_in,
                              void* d_out, int out_size) {
    const float* x_in        = (const float*)d_in[0];
    const float* state_num   = (const float*)d_in[1];
    const float* state_den   = (const float*)d_in[2];
    const float* pred        = (const float*)d_in[3];
    const float* norm_w      = (const float*)d_in[4];
    const float* Wr          = (const float*)d_in[5];
    const float* Wk          = (const float*)d_in[6];
    const float* Wv          = (const float*)d_in[7];
    const float* Wo          = (const float*)d_in[8];
    const float* decay_param = (const float*)d_in[9];
    const float* W_time      = (const float*)d_in[10];
    const float* step_pos    = (const float*)d_in[11];
    const int*   dt          = (const int*)d_in[12];
    float* out = (float*)d_out;

    k_rms<<<1, 1024>>>(x_in, pred, norm_w);
    k_mv3<<<3 * D, 256>>>(Wr, Wk, Wv, state_num, state_den,
                          decay_param, W_time, step_pos, dt);
    k_mv_o<<<D, 256>>>(Wo, out);
}

// round 8
// speedup vs baseline: 1.3226x; 1.3226x over previous
#include <cuda_runtime.h>
#include <math.h>

#define D 8192
#define M_TIME 16
#define RMS_EPS 1e-6f
#define DEN_EPS 1e-9f
#define KTOP 1024  // D/8

// Scratch (no allocations allowed)
__device__ __align__(16) float g_x[D];
__device__ __align__(16) float g_r[D];
__device__ __align__(16) float g_k[D];
__device__ __align__(16) float g_v[D];
__device__ __align__(16) float g_y[D];
__device__ __align__(16) float g_h[D];

__device__ __forceinline__ float warp_sum(float v) {
    #pragma unroll
    for (int o = 16; o > 0; o >>= 1) v += __shfl_down_sync(0xffffffffu, v, o);
    return v;
}

// ---------------------------------------------------------------------------
// K1: x = rmsnorm(x_in + pred) * norm_w      (1 block, 1024 threads)
// ---------------------------------------------------------------------------
__global__ void k_rms(const float* __restrict__ x_in,
                      const float* __restrict__ pred,
                      const float* __restrict__ norm_w) {
    __shared__ float sh[32];
    __shared__ float s_inv;
    const int t = threadIdx.x;  // 1024
    float vals[8];
    float acc = 0.f;
    #pragma unroll
    for (int j = 0; j < 8; j++) {
        int i = t + j * 1024;
        float a = x_in[i] + pred[i];
        vals[j] = a;
        acc = fmaf(a, a, acc);
    }
    acc = warp_sum(acc);
    const int lane = t & 31, wid = t >> 5;
    if (lane == 0) sh[wid] = acc;
    __syncthreads();
    if (wid == 0) {
        float v = sh[lane];
        v = warp_sum(v);
        if (lane == 0) s_inv = rsqrtf(v * (1.0f / D) + RMS_EPS);
    }
    __syncthreads();
    const float inv = s_inv;
    #pragma unroll
    for (int j = 0; j < 8; j++) {
        int i = t + j * 1024;
        g_x[i] = vals[j] * inv * norm_w[i];
    }
}

// ---------------------------------------------------------------------------
// K2: r = sigmoid(Wr@x), k = Wk@x, v = Wv@x   (3*8192 blocks, 256 threads)
//     PDL: wait for k_rms before reading g_x.
// ---------------------------------------------------------------------------
__global__ void __launch_bounds__(256) k_mv3(const float* __restrict__ Wr,
                                             const float* __restrict__ Wk,
                                             const float* __restrict__ Wv) {
    cudaGridDependencySynchronize();
    const int bid = blockIdx.x;
    const int mat = bid >> 13;           // 0..2
    const int row = bid & (D - 1);
    const float* W = (mat == 0 ? Wr : (mat == 1 ? Wk : Wv)) + (size_t)row * D;
    const float4* __restrict__ W4 = (const float4*)W;
    const float4* __restrict__ X4 = (const float4*)g_x;

    const int t = threadIdx.x;
    float acc = 0.f;
    #pragma unroll
    for (int j = 0; j < D / 4 / 256; j++) {  // 8 iterations
        int idx = t + j * 256;
        float4 w = W4[idx];
        float4 x = X4[idx];
        acc = fmaf(w.x, x.x, acc);
        acc = fmaf(w.y, x.y, acc);
        acc = fmaf(w.z, x.z, acc);
        acc = fmaf(w.w, x.w, acc);
    }
    __shared__ float sh[8];
    acc = warp_sum(acc);
    const int lane = t & 31, wid = t >> 5;
    if (lane == 0) sh[wid] = acc;
    __syncthreads();
    if (t == 0) {
        float s = sh[0];
        #pragma unroll
        for (int i = 1; i < 8; i++) s += sh[i];
        if (mat == 0)      g_r[row] = 1.0f / (1.0f + __expf(-s));
        else if (mat == 1) g_k[row] = s;
        else               g_v[row] = s;
    }
}

// ---------------------------------------------------------------------------
// K3: decay/RoPE/gating -> y                 (32 blocks, 256 threads)
// ---------------------------------------------------------------------------
__global__ void k_gate(const float* __restrict__ state_num,
                       const float* __restrict__ state_den,
                       const float* __restrict__ decay_param,
                       const float* __restrict__ W_time,
                       const float* __restrict__ step_pos,
                       const int*   __restrict__ dt) {
    cudaGridDependencySynchronize();
    const int i = blockIdx.x * blockDim.x + threadIdx.x;
    if (i >= D) return;

    float s = 1.0f / (1.0f + expf(-decay_param[i]));
    float lam = s * s;
    float mul = 1.0f;
    int n = dt[0];
    for (int j = 0; j < n; j++) mul *= lam;

    float v = g_v[i];
    if (i < 2 * M_TIME) {
        int p = i >> 1;
        float th = step_pos[0] * W_time[p];
        float c, sn_;
        sincosf(th, &sn_, &c);
        float v0 = g_v[2 * p];
        float v1 = g_v[2 * p + 1];
        v = (i & 1) ? (v0 * sn_ + v1 * c) : (v0 * c - v1 * sn_);
    }

    float w = expf(g_k[i]);
    float num = state_num[i] * mul * lam + w * v;
    float den = state_den[i] * mul * lam + w;
    g_y[i] = g_r[i] * (num / (den + DEN_EPS));
}

// ---------------------------------------------------------------------------
// K4: h = x + Wo@y                           (8192 blocks, 256 threads)
//     PDL: wait for k_gate before reading g_y.
// ---------------------------------------------------------------------------
__global__ void __launch_bounds__(256) k_mv_o(const float* __restrict__ Wo) {
    cudaGridDependencySynchronize();
    const int row = blockIdx.x;
    const float4* __restrict__ W4 = (const float4*)(Wo + (size_t)row * D);
    const float4* __restrict__ Y4 = (const float4*)g_y;

    const int t = threadIdx.x;
    float acc = 0.f;
    #pragma unroll
    for (int j = 0; j < D / 4 / 256; j++) {
        int idx = t + j * 256;
        float4 w = W4[idx];
        float4 y = Y4[idx];
        acc = fmaf(w.x, y.x, acc);
        acc = fmaf(w.y, y.y, acc);
        acc = fmaf(w.z, y.z, acc);
        acc = fmaf(w.w, y.w, acc);
    }
    __shared__ float sh[8];
    acc = warp_sum(acc);
    const int lane = t & 31, wid = t >> 5;
    if (lane == 0) sh[wid] = acc;
    __syncthreads();
    if (t == 0) {
        float s = sh[0];
        #pragma unroll
        for (int i = 1; i < 8; i++) s += sh[i];
        g_h[row] = g_x[row] + s;
    }
}

// ---------------------------------------------------------------------------
// K5: kWTA — exact k-th largest |h| via 4x8-bit radix select with parallel
//     suffix-scan bucket selection, then threshold. (1 block, 1024 threads)
//     PDL: wait for k_mv_o before reading g_h.
// ---------------------------------------------------------------------------
__global__ void k_kwta(float* __restrict__ out) {
    cudaGridDependencySynchronize();
    __shared__ unsigned hist[256];
    __shared__ unsigned wsum[8];
    __shared__ unsigned s_prefix, s_k;
    const int t = threadIdx.x;  // 1024
    const int lane = t & 31, wid = t >> 5;

    unsigned bits[8];
    #pragma unroll
    for (int j = 0; j < 8; j++)
        bits[j] = __float_as_uint(fabsf(g_h[t + j * 1024]));

    unsigned prefix = 0;
    unsigned kk = KTOP;
    #pragma unroll
    for (int shift = 24; shift >= 0; shift -= 8) {
        if (t < 256) hist[t] = 0;
        __syncthreads();
        unsigned mask = (shift == 24) ? 0u : (~0u << (shift + 8));
        #pragma unroll
        for (int j = 0; j < 8; j++) {
            if ((bits[j] & mask) == prefix)
                atomicAdd(&hist[(bits[j] >> shift) & 255u], 1u);
        }
        __syncthreads();
        if (t < 256) {
            unsigned h = hist[t];
            unsigned v = h;
            #pragma unroll
            for (int o = 1; o < 32; o <<= 1) {
                unsigned u = __shfl_down_sync(0xffffffffu, v, o);
                if (lane + o < 32) v += u;
            }
            if (lane == 0) wsum[wid] = v;   // warp suffix totals
            __syncwarp();
        }
        __syncthreads();
        if (t < 256) {
            unsigned hi = 0;
            #pragma unroll
            for (int w = 0; w < 8; w++)
                if (w > wid) hi += wsum[w];
            unsigned h = hist[t];
            unsigned v = h;
            #pragma unroll
            for (int o = 1; o < 32; o <<= 1) {
                unsigned u = __shfl_down_sync(0xffffffffu, v, o);
                if (lane + o < 32) v += u;
            }
            unsigned S = v + hi;            // S[t]
            if (S >= kk && (S - h) < kk) {
                s_prefix = prefix | ((unsigned)t << shift);
                s_k = kk - (S - h);
            }
        }
        __syncthreads();
        prefix = s_prefix;
        kk = s_k;
        __syncthreads();
    }

    const float thr = __uint_as_float(prefix);
    #pragma unroll
    for (int j = 0; j < 8; j++) {
        int i = t + j * 1024;
        float h = g_h[i];
        out[i] = (fabsf(h) >= thr) ? h : 0.0f;
    }
}

// ---------------------------------------------------------------------------
template <typename F, typename... Args>
static inline void launch_pdl(F func, dim3 grid, dim3 block, Args... args) {
    cudaLaunchConfig_t cfg = {};
    cfg.gridDim = grid;
    cfg.blockDim = block;
    cfg.dynamicSmemBytes = 0;
    cudaLaunchAttribute attr[1];
    attr[0].id = cudaLaunchAttributeProgrammaticStreamSerialization;
    attr[0].val.programmaticStreamSerializationAllowed = 1;
    cfg.attrs = attr;
    cfg.numAttrs = 1;
    cudaLaunchKernelEx(&cfg, func, args...);
}

extern "C" void kernel_launch(void* const* d_in, const int* in_sizes, int n_in,
                              void* d_out, int out_size) {
    const float* x_in        = (const float*)d_in[0];
    const float* state_num   = (const float*)d_in[1];
    const float* state_den   = (const float*)d_in[2];
    const float* pred        = (const float*)d_in[3];
    const float* norm_w      = (const float*)d_in[4];
    const float* Wr          = (const float*)d_in[5];
    const float* Wk          = (const float*)d_in[6];
    const float* Wv          = (const float*)d_in[7];
    const float* Wo          = (const float*)d_in[8];
    const float* decay_param = (const float*)d_in[9];
    const float* W_time      = (const float*)d_in[10];
    const float* step_pos    = (const float*)d_in[11];
    const int*   dt          = (const int*)d_in[12];
    float* out = (float*)d_out;

    k_rms<<<1, 1024>>>(x_in, pred, norm_w);
    launch_pdl(k_mv3, dim3(3 * D), dim3(256), Wr, Wk, Wv);
    launch_pdl(k_gate, dim3(D / 256), dim3(256), state_num, state_den,
               decay_param, W_time, step_pos, dt);
    launch_pdl(k_mv_o, dim3(D), dim3(256), Wo);
    launch_pdl(k_kwta, dim3(1), dim3(1024), out);
}

// round 9
// speedup vs baseline: 1.3511x; 1.0216x over previous
#include <cuda_runtime.h>
#include <math.h>

#define D 8192
#define M_TIME 16
#define RMS_EPS 1e-6f
#define DEN_EPS 1e-9f
#define KTOP 1024  // D/8

// Scratch (no allocations allowed)
__device__ __align__(16) float g_x[D];
__device__ __align__(16) float g_r[D];
__device__ __align__(16) float g_k[D];
__device__ __align__(16) float g_v[D];
__device__ __align__(16) float g_y[D];
__device__ __align__(16) float g_h[D];

__device__ __forceinline__ float warp_sum(float v) {
    #pragma unroll
    for (int o = 16; o > 0; o >>= 1) v += __shfl_down_sync(0xffffffffu, v, o);
    return v;
}

// ---------------------------------------------------------------------------
// K1: x = rmsnorm(x_in + pred) * norm_w      (1 block, 1024 threads)
// ---------------------------------------------------------------------------
__global__ void k_rms(const float* __restrict__ x_in,
                      const float* __restrict__ pred,
                      const float* __restrict__ norm_w) {
    __shared__ float sh[32];
    __shared__ float s_inv;
    const int t = threadIdx.x;  // 1024
    float vals[8];
    float acc = 0.f;
    #pragma unroll
    for (int j = 0; j < 8; j++) {
        int i = t + j * 1024;
        float a = x_in[i] + pred[i];
        vals[j] = a;
        acc = fmaf(a, a, acc);
    }
    acc = warp_sum(acc);
    const int lane = t & 31, wid = t >> 5;
    if (lane == 0) sh[wid] = acc;
    __syncthreads();
    if (wid == 0) {
        float v = sh[lane];
        v = warp_sum(v);
        if (lane == 0) s_inv = rsqrtf(v * (1.0f / D) + RMS_EPS);
    }
    __syncthreads();
    const float inv = s_inv;
    #pragma unroll
    for (int j = 0; j < 8; j++) {
        int i = t + j * 1024;
        g_x[i] = vals[j] * inv * norm_w[i];
    }
}

// ---------------------------------------------------------------------------
// K2: r = sigmoid(Wr@x), k = Wk@x, v = Wv@x   (3*8192 blocks, 256 threads)
//     PDL: prefetch the block's weight slice BEFORE the dependency sync so
//     weight streaming overlaps k_rms; only the g_x read needs the sync.
// ---------------------------------------------------------------------------
__global__ void __launch_bounds__(256) k_mv3(const float* __restrict__ Wr,
                                             const float* __restrict__ Wk,
                                             const float* __restrict__ Wv) {
    const int bid = blockIdx.x;
    const int mat = bid >> 13;           // 0..2
    const int row = bid & (D - 1);
    const float* W = (mat == 0 ? Wr : (mat == 1 ? Wk : Wv)) + (size_t)row * D;
    const float4* __restrict__ W4 = (const float4*)W;
    const float4* __restrict__ X4 = (const float4*)g_x;
    const int t = threadIdx.x;

    float4 w[8];
    #pragma unroll
    for (int j = 0; j < 8; j++) w[j] = W4[t + j * 256];

    cudaGridDependencySynchronize();

    float acc = 0.f;
    #pragma unroll
    for (int j = 0; j < 8; j++) {
        float4 x = X4[t + j * 256];
        acc = fmaf(w[j].x, x.x, acc);
        acc = fmaf(w[j].y, x.y, acc);
        acc = fmaf(w[j].z, x.z, acc);
        acc = fmaf(w[j].w, x.w, acc);
    }
    __shared__ float sh[8];
    acc = warp_sum(acc);
    const int lane = t & 31, wid = t >> 5;
    if (lane == 0) sh[wid] = acc;
    __syncthreads();
    if (t == 0) {
        float s = sh[0];
        #pragma unroll
        for (int i = 1; i < 8; i++) s += sh[i];
        if (mat == 0)      g_r[row] = 1.0f / (1.0f + __expf(-s));
        else if (mat == 1) g_k[row] = s;
        else               g_v[row] = s;
    }
}

// ---------------------------------------------------------------------------
// K3: decay/RoPE/gating -> y                 (32 blocks, 256 threads)
//     PDL: prefetch independent inputs before syncing on mv3's outputs.
// ---------------------------------------------------------------------------
__global__ void k_gate(const float* __restrict__ state_num,
                       const float* __restrict__ state_den,
                       const float* __restrict__ decay_param,
                       const float* __restrict__ W_time,
                       const float* __restrict__ step_pos,
                       const int*   __restrict__ dt) {
    const int i = blockIdx.x * blockDim.x + threadIdx.x;

    // Independent of mv3 outputs — issue before the dependency sync.
    float sn_in = state_num[i];
    float sd_in = state_den[i];
    float dp    = decay_param[i];
    int   n     = dt[0];
    float sp    = step_pos[0];

    float s = 1.0f / (1.0f + expf(-dp));
    float lam = s * s;
    float mul = 1.0f;
    for (int j = 0; j < n; j++) mul *= lam;

    cudaGridDependencySynchronize();

    float v = g_v[i];
    if (i < 2 * M_TIME) {
        int p = i >> 1;
        float th = sp * W_time[p];
        float c, sn_;
        sincosf(th, &sn_, &c);
        float v0 = g_v[2 * p];
        float v1 = g_v[2 * p + 1];
        v = (i & 1) ? (v0 * sn_ + v1 * c) : (v0 * c - v1 * sn_);
    }

    float w = expf(g_k[i]);
    float num = sn_in * mul * lam + w * v;
    float den = sd_in * mul * lam + w;
    g_y[i] = g_r[i] * (num / (den + DEN_EPS));
}

// ---------------------------------------------------------------------------
// K4: h = x + Wo@y                           (8192 blocks, 256 threads)
//     PDL: prefetch Wo slice before syncing on k_gate.
// ---------------------------------------------------------------------------
__global__ void __launch_bounds__(256) k_mv_o(const float* __restrict__ Wo) {
    const int row = blockIdx.x;
    const float4* __restrict__ W4 = (const float4*)(Wo + (size_t)row * D);
    const float4* __restrict__ Y4 = (const float4*)g_y;
    const int t = threadIdx.x;

    float4 w[8];
    #pragma unroll
    for (int j = 0; j < 8; j++) w[j] = W4[t + j * 256];

    cudaGridDependencySynchronize();

    float acc = 0.f;
    #pragma unroll
    for (int j = 0; j < 8; j++) {
        float4 y = Y4[t + j * 256];
        acc = fmaf(w[j].x, y.x, acc);
        acc = fmaf(w[j].y, y.y, acc);
        acc = fmaf(w[j].z, y.z, acc);
        acc = fmaf(w[j].w, y.w, acc);
    }
    __shared__ float sh[8];
    acc = warp_sum(acc);
    const int lane = t & 31, wid = t >> 5;
    if (lane == 0) sh[wid] = acc;
    __syncthreads();
    if (t == 0) {
        float s = sh[0];
        #pragma unroll
        for (int i = 1; i < 8; i++) s += sh[i];
        g_h[row] = g_x[row] + s;
    }
}

// ---------------------------------------------------------------------------
// K5: kWTA — exact k-th largest |h| via 4x8-bit radix select with parallel
//     suffix-scan bucket selection, then threshold. (1 block, 1024 threads)
// ---------------------------------------------------------------------------
__global__ void k_kwta(float* __restrict__ out) {
    cudaGridDependencySynchronize();
    __shared__ unsigned hist[256];
    __shared__ unsigned wsum[8];
    __shared__ unsigned s_prefix, s_k;
    const int t = threadIdx.x;  // 1024
    const int lane = t & 31, wid = t >> 5;

    unsigned bits[8];
    #pragma unroll
    for (int j = 0; j < 8; j++)
        bits[j] = __float_as_uint(fabsf(g_h[t + j * 1024]));

    unsigned prefix = 0;
    unsigned kk = KTOP;
    #pragma unroll
    for (int shift = 24; shift >= 0; shift -= 8) {
        if (t < 256) hist[t] = 0;
        __syncthreads();
        unsigned mask = (shift == 24) ? 0u : (~0u << (shift + 8));
        #pragma unroll
        for (int j = 0; j < 8; j++) {
            if ((bits[j] & mask) == prefix)
                atomicAdd(&hist[(bits[j] >> shift) & 255u], 1u);
        }
        __syncthreads();
        if (t < 256) {
            unsigned h = hist[t];
            unsigned v = h;
            #pragma unroll
            for (int o = 1; o < 32; o <<= 1) {
                unsigned u = __shfl_down_sync(0xffffffffu, v, o);
                if (lane + o < 32) v += u;
            }
            if (lane == 0) wsum[wid] = v;   // warp suffix totals
            __syncwarp();
        }
        __syncthreads();
        if (t < 256) {
            unsigned hi = 0;
            #pragma unroll
            for (int w = 0; w < 8; w++)
                if (w > wid) hi += wsum[w];
            unsigned h = hist[t];
            unsigned v = h;
            #pragma unroll
            for (int o = 1; o < 32; o <<= 1) {
                unsigned u = __shfl_down_sync(0xffffffffu, v, o);
                if (lane + o < 32) v += u;
            }
            unsigned S = v + hi;            // S[t]
            if (S >= kk && (S - h) < kk) {
                s_prefix = prefix | ((unsigned)t << shift);
                s_k = kk - (S - h);
            }
        }
        __syncthreads();
        prefix = s_prefix;
        kk = s_k;
        __syncthreads();
    }

    const float thr = __uint_as_float(prefix);
    #pragma unroll
    for (int j = 0; j < 8; j++) {
        int i = t + j * 1024;
        float h = g_h[i];
        out[i] = (fabsf(h) >= thr) ? h : 0.0f;
    }
}

// ---------------------------------------------------------------------------
template <typename F, typename... Args>
static inline void launch_pdl(F func, dim3 grid, dim3 block, Args... args) {
    cudaLaunchConfig_t cfg = {};
    cfg.gridDim = grid;
    cfg.blockDim = block;
    cfg.dynamicSmemBytes = 0;
    cudaLaunchAttribute attr[1];
    attr[0].id = cudaLaunchAttributeProgrammaticStreamSerialization;
    attr[0].val.programmaticStreamSerializationAllowed = 1;
    cfg.attrs = attr;
    cfg.numAttrs = 1;
    cudaLaunchKernelEx(&cfg, func, args...);
}

extern "C" void kernel_launch(void* const* d_in, const int* in_sizes, int n_in,
                              void* d_out, int out_size) {
    const float* x_in        = (const float*)d_in[0];
    const float* state_num   = (const float*)d_in[1];
    const float* state_den   = (const float*)d_in[2];
    const float* pred        = (const float*)d_in[3];
    const float* norm_w      = (const float*)d_in[4];
    const float* Wr          = (const float*)d_in[5];
    const float* Wk          = (const float*)d_in[6];
    const float* Wv          = (const float*)d_in[7];
    const float* Wo          = (const float*)d_in[8];
    const float* decay_param = (const float*)d_in[9];
    const float* W_time      = (const float*)d_in[10];
    const float* step_pos    = (const float*)d_in[11];
    const int*   dt          = (const int*)d_in[12];
    float* out = (float*)d_out;

    k_rms<<<1, 1024>>>(x_in, pred, norm_w);
    launch_pdl(k_mv3, dim3(3 * D), dim3(256), Wr, Wk, Wv);
    launch_pdl(k_gate, dim3(D / 256), dim3(256), state_num, state_den,
               decay_param, W_time, step_pos, dt);
    launch_pdl(k_mv_o, dim3(D), dim3(256), Wo);
    launch_pdl(k_kwta, dim3(1), dim3(1024), out);
}